// round 15
// baseline (speedup 1.0000x reference)
#include <cuda_runtime.h>
#include <cuda_fp16.h>
#include <cstdint>

// Grouped GEMM out[16384,4096]: 8 groups of [2048x4096] @ w[g][4096x4096], fp32 io.
// Pass 1: fp32 -> fp16 scratch (DRAM-bound ~81%, ~175us).
// Pass 2: fp16 HMMA m16n8k16, CTA 128x128, BK=64, 3-stage mbarrier ring,
// 2 CTAs/SM, early empty-arrive. R15: production DISTRIBUTED across the 8
// math warps (8 cp.async each, distance-2) -- removes the R13 hotspot where
// both CTAs' producer warps sat on SMSP0 issuing ~1024 cyc/kt of LDGSTS,
// starving SMSP0's math warps and gating the whole ring.

#define TOK   16384
#define INF   4096
#define OUTF  4096
#define NG    8

#define BM    128
#define BN    128
#define BK    64
#define KT    (INF / BK)          // 64 k-tiles

#define SAH   72                  // A smem row stride (halves): 144B
#define SBH   136                 // B smem row stride (halves): 272B
#define A_BYTES (BM * SAH * 2)    // 18432
#define B_BYTES (BK * SBH * 2)    // 17408
#define STAGE_BYTES (A_BYTES + B_BYTES)       // 35840
#define STAGES 3
#define SMEM_BYTES (1024 + STAGES * STAGE_BYTES)  // 108544 -> 2 CTAs/SM
#define NTHREADS 256              // 8 warps, all produce + consume

__device__ __align__(16) __half g_xh[(size_t)TOK * INF];
__device__ __align__(16) __half g_wh[(size_t)NG * INF * OUTF];

// ---------------- ncu alignment dummy ----------------
__global__ void align_dummy() {}

// ---------------- pass 1: fp32 -> fp16 ----------------
__global__ void cvt_f32_f16(const float* __restrict__ src, __half* __restrict__ dst,
                            size_t n8) {
    size_t i = (size_t)blockIdx.x * blockDim.x + threadIdx.x;
    const size_t stride = (size_t)gridDim.x * blockDim.x;
    for (; i < n8; i += stride) {
        float4 v0 = reinterpret_cast<const float4*>(src)[2 * i];
        float4 v1 = reinterpret_cast<const float4*>(src)[2 * i + 1];
        __half2 h0 = __floats2half2_rn(v0.x, v0.y);
        __half2 h1 = __floats2half2_rn(v0.z, v0.w);
        __half2 h2 = __floats2half2_rn(v1.x, v1.y);
        __half2 h3 = __floats2half2_rn(v1.z, v1.w);
        uint4 u;
        u.x = *reinterpret_cast<uint32_t*>(&h0);
        u.y = *reinterpret_cast<uint32_t*>(&h1);
        u.z = *reinterpret_cast<uint32_t*>(&h2);
        u.w = *reinterpret_cast<uint32_t*>(&h3);
        reinterpret_cast<uint4*>(dst)[i] = u;
    }
}

// ---------------- pass 2: fp16 HMMA GEMM ----------------
__device__ __forceinline__ uint32_t smem_u32(const void* p) {
    uint32_t a;
    asm("{ .reg .u64 t; cvta.to.shared.u64 t, %1; cvt.u32.u64 %0, t; }"
        : "=r"(a) : "l"(p));
    return a;
}

#define CPA16(dst, src) \
    asm volatile("cp.async.cg.shared.global [%0], [%1], 16;" :: "r"(dst), "l"(src))

__device__ __forceinline__ void mbar_wait(uint32_t addr, uint32_t phase) {
    asm volatile(
        "{ .reg .pred P;\n"
        "WL_%=: mbarrier.try_wait.parity.acquire.cta.shared::cta.b64 P, [%0], %1, 0x989680;\n"
        "@P bra.uni WD_%=;\n"
        "bra.uni WL_%=;\n"
        "WD_%=: }\n" :: "r"(addr), "r"(phase) : "memory");
}

#define MBAR_ARRIVE(addr) \
    asm volatile("mbarrier.arrive.release.cta.shared::cta.b64 _, [%0];" :: "r"(addr) : "memory")

#define LDSM_X4(r0, r1, r2, r3, a)                                              \
    asm volatile("ldmatrix.sync.aligned.m8n8.x4.shared.b16 {%0,%1,%2,%3}, [%4];" \
                 : "=r"(r0), "=r"(r1), "=r"(r2), "=r"(r3) : "r"(a))

#define LDSM_X4T(r0, r1, r2, r3, a)                                                   \
    asm volatile("ldmatrix.sync.aligned.m8n8.x4.trans.shared.b16 {%0,%1,%2,%3}, [%4];" \
                 : "=r"(r0), "=r"(r1), "=r"(r2), "=r"(r3) : "r"(a))

__device__ __forceinline__ void mma16816(float* d, const uint32_t* a, const uint32_t* b) {
    asm volatile(
        "mma.sync.aligned.m16n8k16.row.col.f32.f16.f16.f32 "
        "{%0,%1,%2,%3}, {%4,%5,%6,%7}, {%8,%9}, {%0,%1,%2,%3};"
        : "+f"(d[0]), "+f"(d[1]), "+f"(d[2]), "+f"(d[3])
        : "r"(a[0]), "r"(a[1]), "r"(a[2]), "r"(a[3]), "r"(b[0]), "r"(b[1]));
}

extern "C" __global__ void __launch_bounds__(NTHREADS, 2)
grouped_gemm_f16(float* __restrict__ out) {
    extern __shared__ char sm[];
    const uint32_t smb = smem_u32(sm);       // full[s]=smb+8s, empty[s]=smb+32+8s
    const uint32_t data = smb + 1024;

    const int t = threadIdx.x;
    const int lane = t & 31;
    const int wid = t >> 5;          // 8 warps: 2 (m) x 4 (n)
    const int wm = wid & 1;
    const int wn = wid >> 1;

    const int bid = blockIdx.x;
    const int nt = bid & 31;         // nt-inner: wave shares A panels in L2
    const int mt = bid >> 5;
    const int g  = mt >> 4;

    const __half* xg = g_xh + (size_t)mt * BM * INF;
    const __half* wg = g_wh + (size_t)g * INF * OUTF + (size_t)nt * BN;

    if (t == 0) {
#pragma unroll
        for (int s = 0; s < STAGES; s++) {
            asm volatile("mbarrier.init.shared.b64 [%0], 256;" :: "r"(smb + s * 8) : "memory");
            asm volatile("mbarrier.init.shared.b64 [%0], 8;"   :: "r"(smb + 32 + s * 8) : "memory");
        }
    }
    __syncthreads();

    // per-thread slice of one k-tile (8 x 16B cp.async), same for every warp
    const uint32_t aDst0 = (uint32_t)(t >> 3) * (SAH * 2) + (uint32_t)(t & 7) * 16;
    const uint32_t bDst0 = A_BYTES + (uint32_t)(t >> 4) * (SBH * 2) +
                           (uint32_t)(t & 15) * 16;
    const __half* aSrc0 = xg + (size_t)(t >> 3) * INF + (t & 7) * 8;
    const __half* bSrc0 = wg + (size_t)(t >> 4) * OUTF + (t & 15) * 8;

    auto produce_issue = [&](int j, uint32_t sb) {
        const __half* xk = aSrc0 + (size_t)j * BK;
        const __half* wk = bSrc0 + (size_t)j * BK * OUTF;
#pragma unroll
        for (int i = 0; i < 4; i++)          // A rows (t>>3) + 32*i
            CPA16(sb + aDst0 + (uint32_t)i * (32 * SAH * 2),
                  xk + (size_t)(32 * i) * INF);
#pragma unroll
        for (int i = 0; i < 4; i++)          // B k-rows (t>>4) + 16*i
            CPA16(sb + bDst0 + (uint32_t)i * (16 * SBH * 2),
                  wk + (size_t)(16 * i) * OUTF);
    };

    // prologue: produce k-tiles 0,1 (empty waits pass on fresh barriers, parity 1)
    int sp = 0, phP = 1;
#pragma unroll
    for (int j = 0; j < 2; j++) {
        mbar_wait(smb + 32 + sp * 8, (uint32_t)phP);
        produce_issue(j, data + (uint32_t)sp * STAGE_BYTES);
        asm volatile("cp.async.commit_group;" ::: "memory");
        sp++;
    }

    float acc[4][4][4];
#pragma unroll
    for (int mi = 0; mi < 4; mi++)
#pragma unroll
        for (int ni = 0; ni < 4; ni++)
#pragma unroll
            for (int q = 0; q < 4; q++) acc[mi][ni][q] = 0.0f;

    const uint32_t aOff =
        (uint32_t)(wm * 64 + (lane & 7) + ((lane >> 3) & 1) * 8) * (SAH * 2) +
        (uint32_t)((lane >> 4) & 1) * 16;
    const uint32_t bOff = A_BYTES +
        (uint32_t)((lane & 7) + ((lane >> 3) & 1) * 8) * (SBH * 2) +
        (uint32_t)(wn * 32 + ((lane >> 4) & 1) * 8) * 2;

    int sc = 0, phC = 0;
    for (int kt = 0; kt < KT; kt++) {
        // produce k-tile kt+2 (distance 2) into stage (kt+2)%3
        if (kt + 2 < KT) {
            mbar_wait(smb + 32 + sp * 8, (uint32_t)phP);     // empty[(kt+2)%3]
            produce_issue(kt + 2, data + (uint32_t)sp * STAGE_BYTES);
        }
        asm volatile("cp.async.commit_group;" ::: "memory"); // uniform group count
        if (++sp == STAGES) { sp = 0; phP ^= 1; }

        // my copies for k-tile kt are now 2 groups old -> complete
        asm volatile("cp.async.wait_group 2;" ::: "memory");
        MBAR_ARRIVE(smb + sc * 8);                           // full[kt%3], all lanes

        mbar_wait(smb + sc * 8, (uint32_t)phC);              // all 256 arrivals
        const uint32_t stage = data + (uint32_t)sc * STAGE_BYTES;

#pragma unroll
        for (int ks = 0; ks < 4; ks++) {   // BK=64 -> 4 x k16
            uint32_t a[4][4], b[2][4];
#pragma unroll
            for (int np = 0; np < 2; np++)
                LDSM_X4T(b[np][0], b[np][1], b[np][2], b[np][3],
                         stage + bOff + (uint32_t)ks * (16 * SBH * 2) +
                             (uint32_t)np * 32);
#pragma unroll
            for (int mi = 0; mi < 4; mi++)
                LDSM_X4(a[mi][0], a[mi][1], a[mi][2], a[mi][3],
                        stage + aOff + (uint32_t)mi * (16 * SAH * 2) +
                            (uint32_t)ks * 32);

            // all of this warp's reads of stage sc are issued after the last ldsm
            if (ks == 3 && lane == 0) MBAR_ARRIVE(smb + 32 + sc * 8);  // empty[sc]

#pragma unroll
            for (int mi = 0; mi < 4; mi++)
#pragma unroll
                for (int np = 0; np < 2; np++) {
                    mma16816(acc[mi][2 * np],     a[mi], &b[np][0]);
                    mma16816(acc[mi][2 * np + 1], a[mi], &b[np][2]);
                }
        }

        if (++sc == STAGES) { sc = 0; phC ^= 1; }
    }

    const int r0 = mt * BM + wm * 64 + (lane >> 2);
    const int c0 = nt * BN + wn * 32 + 2 * (lane & 3);
#pragma unroll
    for (int mi = 0; mi < 4; mi++)
#pragma unroll
        for (int ni = 0; ni < 4; ni++) {
            size_t base = (size_t)(r0 + mi * 16) * OUTF + c0 + ni * 8;
            *reinterpret_cast<float2*>(out + base) =
                make_float2(acc[mi][ni][0], acc[mi][ni][1]);
            *reinterpret_cast<float2*>(out + base + 8 * OUTF) =
                make_float2(acc[mi][ni][2], acc[mi][ni][3]);
        }
}

extern "C" void kernel_launch(void* const* d_in, const int* in_sizes, int n_in,
                              void* d_out, int out_size) {
    const float* x = (const float*)d_in[0];
    const float* w = (const float*)d_in[1];
    float* out = (float*)d_out;

    __half* xh = nullptr;
    __half* wh = nullptr;
    cudaGetSymbolAddress((void**)&xh, g_xh);
    cudaGetSymbolAddress((void**)&wh, g_wh);

    align_dummy<<<1, 32>>>();   // keeps ncu -s5-c1 on the GEMM launch

    cvt_f32_f16<<<4096, 256>>>(x, xh, (size_t)TOK * INF / 8);
    cvt_f32_f16<<<8192, 256>>>(w, wh, (size_t)NG * INF * OUTF / 8);

    cudaFuncSetAttribute(grouped_gemm_f16,
                         cudaFuncAttributeMaxDynamicSharedMemorySize, SMEM_BYTES);
    dim3 grid((TOK / BM) * (OUTF / BN));   // 128 * 32 = 4096
    grouped_gemm_f16<<<grid, NTHREADS, SMEM_BYTES>>>(out);
}

// round 16
// speedup vs baseline: 1.0831x; 1.0831x over previous
#include <cuda_runtime.h>
#include <cuda_fp16.h>
#include <cstdint>

// Grouped GEMM out[16384,4096]: 8 groups of [2048x4096] @ w[g][4096x4096], fp32 io.
// Pass 1: fp32 -> fp16 scratch (DRAM-bound ~81%, ~175us).
// Pass 2: fp16 HMMA m16n8k16, CTA 128x128, BK=64, 3-stage mbarrier ring,
// 2 CTAs/SM, early empty-arrive (R13 winner). R16: TWO producer warps --
// wid 8 loads A (SMSP0), wid 9 loads B (SMSP1) -- halves per-SMSP LDGSTS
// issue pressure (512->256 cyc/kt/CTA) that starved SMSP0's math warps,
// while keeping produce fully decoupled from consume (the R15 mistake).

#define TOK   16384
#define INF   4096
#define OUTF  4096
#define NG    8

#define BM    128
#define BN    128
#define BK    64
#define KT    (INF / BK)          // 64 k-tiles

#define SAH   72                  // A smem row stride (halves): 144B
#define SBH   136                 // B smem row stride (halves): 272B
#define A_BYTES (BM * SAH * 2)    // 18432
#define B_BYTES (BK * SBH * 2)    // 17408
#define STAGE_BYTES (A_BYTES + B_BYTES)       // 35840
#define STAGES 3
#define SMEM_BYTES (1024 + STAGES * STAGE_BYTES)  // 108544 -> 2 CTAs/SM
#define NTHREADS 320              // 8 math warps + 2 producer warps

__device__ __align__(16) __half g_xh[(size_t)TOK * INF];
__device__ __align__(16) __half g_wh[(size_t)NG * INF * OUTF];

// ---------------- ncu alignment dummy ----------------
__global__ void align_dummy() {}

// ---------------- pass 1: fp32 -> fp16 ----------------
__global__ void cvt_f32_f16(const float* __restrict__ src, __half* __restrict__ dst,
                            size_t n8) {
    size_t i = (size_t)blockIdx.x * blockDim.x + threadIdx.x;
    const size_t stride = (size_t)gridDim.x * blockDim.x;
    for (; i < n8; i += stride) {
        float4 v0 = reinterpret_cast<const float4*>(src)[2 * i];
        float4 v1 = reinterpret_cast<const float4*>(src)[2 * i + 1];
        __half2 h0 = __floats2half2_rn(v0.x, v0.y);
        __half2 h1 = __floats2half2_rn(v0.z, v0.w);
        __half2 h2 = __floats2half2_rn(v1.x, v1.y);
        __half2 h3 = __floats2half2_rn(v1.z, v1.w);
        uint4 u;
        u.x = *reinterpret_cast<uint32_t*>(&h0);
        u.y = *reinterpret_cast<uint32_t*>(&h1);
        u.z = *reinterpret_cast<uint32_t*>(&h2);
        u.w = *reinterpret_cast<uint32_t*>(&h3);
        reinterpret_cast<uint4*>(dst)[i] = u;
    }
}

// ---------------- pass 2: fp16 HMMA GEMM ----------------
__device__ __forceinline__ uint32_t smem_u32(const void* p) {
    uint32_t a;
    asm("{ .reg .u64 t; cvta.to.shared.u64 t, %1; cvt.u32.u64 %0, t; }"
        : "=r"(a) : "l"(p));
    return a;
}

#define CPA16(dst, src) \
    asm volatile("cp.async.cg.shared.global [%0], [%1], 16;" :: "r"(dst), "l"(src))

__device__ __forceinline__ void mbar_wait(uint32_t addr, uint32_t phase) {
    asm volatile(
        "{ .reg .pred P;\n"
        "WL_%=: mbarrier.try_wait.parity.acquire.cta.shared::cta.b64 P, [%0], %1, 0x989680;\n"
        "@P bra.uni WD_%=;\n"
        "bra.uni WL_%=;\n"
        "WD_%=: }\n" :: "r"(addr), "r"(phase) : "memory");
}

#define MBAR_ARRIVE(addr) \
    asm volatile("mbarrier.arrive.release.cta.shared::cta.b64 _, [%0];" :: "r"(addr) : "memory")

#define LDSM_X4(r0, r1, r2, r3, a)                                              \
    asm volatile("ldmatrix.sync.aligned.m8n8.x4.shared.b16 {%0,%1,%2,%3}, [%4];" \
                 : "=r"(r0), "=r"(r1), "=r"(r2), "=r"(r3) : "r"(a))

#define LDSM_X4T(r0, r1, r2, r3, a)                                                   \
    asm volatile("ldmatrix.sync.aligned.m8n8.x4.trans.shared.b16 {%0,%1,%2,%3}, [%4];" \
                 : "=r"(r0), "=r"(r1), "=r"(r2), "=r"(r3) : "r"(a))

__device__ __forceinline__ void mma16816(float* d, const uint32_t* a, const uint32_t* b) {
    asm volatile(
        "mma.sync.aligned.m16n8k16.row.col.f32.f16.f16.f32 "
        "{%0,%1,%2,%3}, {%4,%5,%6,%7}, {%8,%9}, {%0,%1,%2,%3};"
        : "+f"(d[0]), "+f"(d[1]), "+f"(d[2]), "+f"(d[3])
        : "r"(a[0]), "r"(a[1]), "r"(a[2]), "r"(a[3]), "r"(b[0]), "r"(b[1]));
}

extern "C" __global__ void __launch_bounds__(NTHREADS, 2)
grouped_gemm_f16(float* __restrict__ out) {
    extern __shared__ char sm[];
    const uint32_t smb = smem_u32(sm);       // full[s]=smb+8s, empty[s]=smb+32+8s
    const uint32_t data = smb + 1024;

    const int t = threadIdx.x;
    const int lane = t & 31;
    const int wid = t >> 5;          // 0..7 math (2m x 4n), 8: A-prod, 9: B-prod

    const int bid = blockIdx.x;
    const int nt = bid & 31;         // nt-inner: wave shares A panels in L2
    const int mt = bid >> 5;
    const int g  = mt >> 4;

    const __half* xg = g_xh + (size_t)mt * BM * INF;
    const __half* wg = g_wh + (size_t)g * INF * OUTF + (size_t)nt * BN;

    if (t == 0) {
#pragma unroll
        for (int s = 0; s < STAGES; s++) {
            asm volatile("mbarrier.init.shared.b64 [%0], 64;" :: "r"(smb + s * 8) : "memory");
            asm volatile("mbarrier.init.shared.b64 [%0], 8;"  :: "r"(smb + 32 + s * 8) : "memory");
        }
    }
    __syncthreads();

    if (wid >= 8) {
        // ---------------- producer warps: wid 8 -> A, wid 9 -> B ----------------
        const bool isA = (wid == 8);
        const uint32_t dst0 = isA
            ? (uint32_t)(lane >> 3) * (SAH * 2) + (uint32_t)(lane & 7) * 16
            : A_BYTES + (uint32_t)(lane >> 4) * (SBH * 2) + (uint32_t)(lane & 15) * 16;
        const __half* src0 = isA
            ? xg + (size_t)(lane >> 3) * INF + (lane & 7) * 8
            : wg + (size_t)(lane >> 4) * OUTF + (lane & 15) * 8;
        const uint32_t dstStep = isA ? (uint32_t)(4 * SAH * 2) : (uint32_t)(2 * SBH * 2);
        const size_t srcStep = isA ? (size_t)4 * INF : (size_t)2 * OUTF;

        int s = 0, phE = 1, ps = 0;
        for (int j = 0; j < KT; j++) {
            mbar_wait(smb + 32 + s * 8, (uint32_t)phE);          // empty[s]
            const uint32_t sb = data + (uint32_t)s * STAGE_BYTES;
            const __half* sk = isA ? src0 + (size_t)j * BK
                                   : src0 + (size_t)j * BK * OUTF;
#pragma unroll
            for (int i = 0; i < 32; i++)
                CPA16(sb + dst0 + (uint32_t)i * dstStep, sk + (size_t)i * srcStep);
            asm volatile("cp.async.commit_group;" ::: "memory");
            if (j > 0) {
                asm volatile("cp.async.wait_group 1;" ::: "memory");  // group j-1 done
                MBAR_ARRIVE(smb + ps * 8);                            // full[j-1]
            }
            ps = s;
            if (++s == STAGES) { s = 0; phE ^= 1; }
        }
        asm volatile("cp.async.wait_group 0;" ::: "memory");
        MBAR_ARRIVE(smb + ps * 8);                                    // full[KT-1]
        return;
    }

    // ---------------- math warps (8): 2m x 4n of 64x32 tiles ----------------
    const int wm = wid & 1;
    const int wn = wid >> 1;

    float acc[4][4][4];
#pragma unroll
    for (int mi = 0; mi < 4; mi++)
#pragma unroll
        for (int ni = 0; ni < 4; ni++)
#pragma unroll
            for (int q = 0; q < 4; q++) acc[mi][ni][q] = 0.0f;

    const uint32_t aOff =
        (uint32_t)(wm * 64 + (lane & 7) + ((lane >> 3) & 1) * 8) * (SAH * 2) +
        (uint32_t)((lane >> 4) & 1) * 16;
    const uint32_t bOff = A_BYTES +
        (uint32_t)((lane & 7) + ((lane >> 3) & 1) * 8) * (SBH * 2) +
        (uint32_t)(wn * 32 + ((lane >> 4) & 1) * 8) * 2;

    int s = 0, ph = 0;
    for (int kt = 0; kt < KT; kt++) {
        mbar_wait(smb + s * 8, (uint32_t)ph);                // full[s]
        const uint32_t stage = data + (uint32_t)s * STAGE_BYTES;

#pragma unroll
        for (int ks = 0; ks < 4; ks++) {   // BK=64 -> 4 x k16
            uint32_t a[4][4], b[2][4];
#pragma unroll
            for (int np = 0; np < 2; np++)
                LDSM_X4T(b[np][0], b[np][1], b[np][2], b[np][3],
                         stage + bOff + (uint32_t)ks * (16 * SBH * 2) +
                             (uint32_t)np * 32);
#pragma unroll
            for (int mi = 0; mi < 4; mi++)
                LDSM_X4(a[mi][0], a[mi][1], a[mi][2], a[mi][3],
                        stage + aOff + (uint32_t)mi * (16 * SAH * 2) +
                            (uint32_t)ks * 32);

            // after the final ldsm of this stage, its smem is free for producers
            if (ks == 3 && lane == 0) MBAR_ARRIVE(smb + 32 + s * 8);  // empty[s]

#pragma unroll
            for (int mi = 0; mi < 4; mi++)
#pragma unroll
                for (int np = 0; np < 2; np++) {
                    mma16816(acc[mi][2 * np],     a[mi], &b[np][0]);
                    mma16816(acc[mi][2 * np + 1], a[mi], &b[np][2]);
                }
        }

        if (++s == STAGES) { s = 0; ph ^= 1; }
    }

    const int r0 = mt * BM + wm * 64 + (lane >> 2);
    const int c0 = nt * BN + wn * 32 + 2 * (lane & 3);
#pragma unroll
    for (int mi = 0; mi < 4; mi++)
#pragma unroll
        for (int ni = 0; ni < 4; ni++) {
            size_t base = (size_t)(r0 + mi * 16) * OUTF + c0 + ni * 8;
            *reinterpret_cast<float2*>(out + base) =
                make_float2(acc[mi][ni][0], acc[mi][ni][1]);
            *reinterpret_cast<float2*>(out + base + 8 * OUTF) =
                make_float2(acc[mi][ni][2], acc[mi][ni][3]);
        }
}

extern "C" void kernel_launch(void* const* d_in, const int* in_sizes, int n_in,
                              void* d_out, int out_size) {
    const float* x = (const float*)d_in[0];
    const float* w = (const float*)d_in[1];
    float* out = (float*)d_out;

    __half* xh = nullptr;
    __half* wh = nullptr;
    cudaGetSymbolAddress((void**)&xh, g_xh);
    cudaGetSymbolAddress((void**)&wh, g_wh);

    align_dummy<<<1, 32>>>();   // keeps ncu -s5-c1 on the GEMM launch

    cvt_f32_f16<<<4096, 256>>>(x, xh, (size_t)TOK * INF / 8);
    cvt_f32_f16<<<8192, 256>>>(w, wh, (size_t)NG * INF * OUTF / 8);

    cudaFuncSetAttribute(grouped_gemm_f16,
                         cudaFuncAttributeMaxDynamicSharedMemorySize, SMEM_BYTES);
    dim3 grid((TOK / BM) * (OUTF / BN));   // 128 * 32 = 4096
    grouped_gemm_f16<<<grid, NTHREADS, SMEM_BYTES>>>(out);
}